// round 4
// baseline (speedup 1.0000x reference)
#include <cuda_runtime.h>
#include <cuda_bf16.h>

// GHM-C loss, single pass:
//   t in {0,1} exactly -> z = (1-2t)*x, g = sigmoid(z), bce = softplus(z).
//   result = sum_b S_b / max(cnt_b * nonempty, 1e-4)  where S_b = sum of bce in bin b.
// Pass 1: per-thread private shared histograms (conflict-free, no atomics in hot loop),
//         block tree-reduce, double global atomics (10 per block).
// Pass 2: tiny finalize kernel -> scalar.

#define BINS      10
#define NTHREADS  256
#define NBLOCKS   888          // 148 SMs * 6 blocks

__device__ double g_cnt[BINS];
__device__ double g_sum[BINS];

__global__ void ghm_zero_kernel() {
    int t = threadIdx.x;
    if (t < BINS) { g_cnt[t] = 0.0; g_sum[t] = 0.0; }
}

__global__ __launch_bounds__(NTHREADS, 6)
void ghm_main_kernel(const float4* __restrict__ xv4,
                     const float4* __restrict__ tv4,
                     int nvec, int n)
{
    __shared__ float2 hist[BINS * NTHREADS];   // [bin][tid] : {count, bce_sum}

    const int tid = threadIdx.x;
    #pragma unroll
    for (int b = 0; b < BINS; ++b)
        hist[b * NTHREADS + tid] = make_float2(0.0f, 0.0f);
    __syncthreads();

    const int stride = gridDim.x * NTHREADS;
    for (int i = blockIdx.x * NTHREADS + tid; i < nvec; i += stride) {
        float4 xv = xv4[i];
        float4 tv = tv4[i];
        float xs[4] = {xv.x, xv.y, xv.z, xv.w};
        float ts[4] = {tv.x, tv.y, tv.z, tv.w};
        #pragma unroll
        for (int k = 0; k < 4; ++k) {
            float xk = xs[k];
            float z  = (ts[k] > 0.5f) ? -xk : xk;   // z = (1-2t)*x, t exactly 0/1
            float az = fabsf(z);
            float u  = __expf(-az);                 // e^{-|z|}  (MUFU.EX2)
            float w  = 1.0f + u;
            float r  = __fdividef(1.0f, w);         // MUFU.RCP path
            float ur = u * r;                       // sigmoid(-|z|)
            float g  = (z >= 0.0f) ? (1.0f - ur) : ur;   // sigmoid(z)
            int bin  = (int)(g * 9.9999f);          // floor, g >= 0
            bin = min(bin, BINS - 1);               // guard approx-rcp overshoot
            float bce = fmaxf(z, 0.0f) + __logf(w); // softplus(z) (MUFU.LG2)

            float2* slot = &hist[bin * NTHREADS + tid];
            float2 h = *slot;
            h.x += 1.0f;
            h.y += bce;
            *slot = h;
        }
    }

    // scalar tail (n not multiple of 4) -- block 0 only
    if (blockIdx.x == 0) {
        int base = nvec * 4;
        int rem  = n - base;
        if (tid < rem) {
            const float* xf = (const float*)xv4;
            const float* tf = (const float*)tv4;
            float xk = xf[base + tid];
            float z  = (tf[base + tid] > 0.5f) ? -xk : xk;
            float az = fabsf(z);
            float u  = __expf(-az);
            float w  = 1.0f + u;
            float r  = __fdividef(1.0f, w);
            float ur = u * r;
            float g  = (z >= 0.0f) ? (1.0f - ur) : ur;
            int bin  = min((int)(g * 9.9999f), BINS - 1);
            float bce = fmaxf(z, 0.0f) + __logf(w);
            float2* slot = &hist[bin * NTHREADS + tid];
            float2 h = *slot;
            h.x += 1.0f;
            h.y += bce;
            *slot = h;
        }
    }
    __syncthreads();

    // tree-reduce over the 256 private histograms
    for (int s = NTHREADS / 2; s > 0; s >>= 1) {
        if (tid < s) {
            #pragma unroll
            for (int b = 0; b < BINS; ++b) {
                float2 a = hist[b * NTHREADS + tid];
                float2 c = hist[b * NTHREADS + tid + s];
                a.x += c.x;
                a.y += c.y;
                hist[b * NTHREADS + tid] = a;
            }
        }
        __syncthreads();
    }

    if (tid < BINS) {
        atomicAdd(&g_cnt[tid], (double)hist[tid * NTHREADS].x);
        atomicAdd(&g_sum[tid], (double)hist[tid * NTHREADS].y);
    }
}

__global__ void ghm_finalize_kernel(float* __restrict__ out) {
    if (threadIdx.x == 0) {
        double ne = 0.0;
        #pragma unroll
        for (int b = 0; b < BINS; ++b)
            if (g_cnt[b] > 0.0) ne += 1.0;
        double res = 0.0;
        #pragma unroll
        for (int b = 0; b < BINS; ++b) {
            double gd = g_cnt[b] * ne;
            if (gd < 1e-4) gd = 1e-4;
            res += g_sum[b] / gd;
        }
        out[0] = (float)res;
    }
}

extern "C" void kernel_launch(void* const* d_in, const int* in_sizes, int n_in,
                              void* d_out, int out_size) {
    const float* x = (const float*)d_in[0];
    const float* t = (const float*)d_in[1];
    int n    = in_sizes[0];
    int nvec = n >> 2;

    ghm_zero_kernel<<<1, 32>>>();
    ghm_main_kernel<<<NBLOCKS, NTHREADS>>>((const float4*)x, (const float4*)t, nvec, n);
    ghm_finalize_kernel<<<1, 32>>>((float*)d_out);
}